// round 8
// baseline (speedup 1.0000x reference)
#include <cuda_runtime.h>
#include <math.h>

// Problem dims (fixed by setup_inputs)
constexpr int B = 8, H = 384, W = 768;
constexpr int HW = H * W;              // 294912
constexpr int NPIX = B * HW;           // 2359296

// Accumulators: 0 photo_fw, 1 photo_bw, 2 census_fw, 3 census_bw, 4 mask_fw_sum, 5 mask_bw_sum
// Zero-initialized at module load; k_final re-zeroes after reading each call.
__device__ double g_acc[6];

// Scratch gray maps (intensity*255) and backward mask
__device__ float g_g1[NPIX];    // gray(img1)*255
__device__ float g_g2[NPIX];    // gray(img2)*255
__device__ float g_g1w[NPIX];   // gray(warp(img1, flow_bw))*255
__device__ float g_g2w[NPIX];   // gray(warp(img2, flow_fw))*255
__device__ float g_maskbw[NPIX];

// ---- packed f32x2 helpers (FFMA2 path — ptxas never emits these from C++) ----
typedef unsigned long long u64;

__device__ __forceinline__ u64 pack2(float lo, float hi) {
    u64 r; asm("mov.b64 %0, {%1, %2};" : "=l"(r) : "f"(lo), "f"(hi)); return r;
}
__device__ __forceinline__ void unpack2(u64 v, float& lo, float& hi) {
    asm("mov.b64 {%0, %1}, %2;" : "=f"(lo), "=f"(hi) : "l"(v));
}
__device__ __forceinline__ u64 add2(u64 a, u64 b) {
    u64 r; asm("add.rn.f32x2 %0, %1, %2;" : "=l"(r) : "l"(a), "l"(b)); return r;
}
__device__ __forceinline__ u64 mul2(u64 a, u64 b) {
    u64 r; asm("mul.rn.f32x2 %0, %1, %2;" : "=l"(r) : "l"(a), "l"(b)); return r;
}
__device__ __forceinline__ u64 fma2(u64 a, u64 b, u64 c) {
    u64 r; asm("fma.rn.f32x2 %0, %1, %2, %3;" : "=l"(r) : "l"(a), "l"(b), "l"(c)); return r;
}

struct Bilin {
    int i00, i01, i10, i11;
    float w00, w01, w10, w11;
};

__device__ __forceinline__ Bilin make_bilin(float fx, float fy, int x, int y) {
    float gx = fminf(fmaxf(fx + (float)x, 0.0f), (float)(W - 1));
    float gy = fminf(fmaxf(fy + (float)y, 0.0f), (float)(H - 1));
    float x0 = floorf(gx), y0 = floorf(gy);
    float wx = gx - x0, wy = gy - y0;
    int x0i = (int)x0, y0i = (int)y0;
    int x1i = min(x0i + 1, W - 1);
    int y1i = min(y0i + 1, H - 1);
    Bilin b;
    b.i00 = y0i * W + x0i;
    b.i01 = y0i * W + x1i;
    b.i10 = y1i * W + x0i;
    b.i11 = y1i * W + x1i;
    float ix = 1.0f - wx, iy = 1.0f - wy;
    b.w00 = ix * iy; b.w01 = wx * iy; b.w10 = ix * wy; b.w11 = wx * wy;
    return b;
}

__device__ __forceinline__ float samp(const float* __restrict__ p, const Bilin& bl) {
    return bl.w00 * __ldg(p + bl.i00) + bl.w01 * __ldg(p + bl.i01)
         + bl.w10 * __ldg(p + bl.i10) + bl.w11 * __ldg(p + bl.i11);
}

__device__ __forceinline__ float warp_reduce(float v) {
    #pragma unroll
    for (int o = 16; o > 0; o >>= 1) v += __shfl_down_sync(0xFFFFFFFFu, v, o);
    return v;
}

// Per-pixel: occ fw/bw, photometric loss partials, gray maps
__global__ void __launch_bounds__(256) k_main(const float* __restrict__ img1,
                                              const float* __restrict__ img2,
                                              const float* __restrict__ ffw,
                                              const float* __restrict__ fbw,
                                              float* __restrict__ out) {
    int i = blockIdx.x * blockDim.x + threadIdx.x;   // grid sized exactly
    int b = i / HW;
    int r = i - b * HW;
    int y = r / W;
    int x = r - y * W;

    const float* f1 = ffw + (size_t)b * 2 * HW;
    const float* f2 = fbw + (size_t)b * 2 * HW;
    float fwx = f1[r],       fwy = f1[HW + r];
    float bwx = f2[r],       bwy = f2[HW + r];

    Bilin bf = make_bilin(fwx, fwy, x, y);
    Bilin bb = make_bilin(bwx, bwy, x, y);

    // occ_fw = compute_occ(flow_fw, flow_bw)
    float bwwx = samp(f2, bf);
    float bwwy = samp(f2 + HW, bf);
    float dx0 = fwx + bwwx, dy0 = fwy + bwwy;
    float mag = dx0 * dx0 + dy0 * dy0;
    float fm  = fwx * fwx + fwy * fwy + bwwx * bwwx + bwwy * bwwy;
    float occf = (mag > fmaf(0.01f, fm, 0.5f)) ? 1.0f : 0.0f;
    out[3 + i] = occf;
    float mfw = 1.0f - occf;

    // occ_bw = compute_occ(flow_bw, flow_fw)
    float fwwx = samp(f1, bb);
    float fwwy = samp(f1 + HW, bb);
    float dx1 = bwx + fwwx, dy1 = bwy + fwwy;
    float mag1 = dx1 * dx1 + dy1 * dy1;
    float fm1  = bwx * bwx + bwy * bwy + fwwx * fwwx + fwwy * fwwy;
    float occb = (mag1 > fmaf(0.01f, fm1, 0.5f)) ? 1.0f : 0.0f;
    float mbw = 1.0f - occb;
    g_maskbw[i] = mbw;

    // image warps + photometric
    const float* i1 = img1 + (size_t)b * 3 * HW;
    const float* i2 = img2 + (size_t)b * 3 * HW;

    float w0 = samp(i2, bf), w1 = samp(i2 + HW, bf), w2 = samp(i2 + 2 * HW, bf);
    float a0 = i1[r], a1 = i1[HW + r], a2 = i1[2 * HW + r];
    float pfw = mfw * (__powf(fabsf(a0 - w0) + 0.01f, 0.4f)
                     + __powf(fabsf(a1 - w1) + 0.01f, 0.4f)
                     + __powf(fabsf(a2 - w2) + 0.01f, 0.4f));
    g_g2w[i] = (0.2989f * w0 + 0.587f * w1 + 0.114f * w2) * 255.0f;
    g_g1[i]  = (0.2989f * a0 + 0.587f * a1 + 0.114f * a2) * 255.0f;

    float v0 = samp(i1, bb), v1 = samp(i1 + HW, bb), v2 = samp(i1 + 2 * HW, bb);
    float c0 = i2[r], c1 = i2[HW + r], c2 = i2[2 * HW + r];
    float pbw = mbw * (__powf(fabsf(c0 - v0) + 0.01f, 0.4f)
                     + __powf(fabsf(c1 - v1) + 0.01f, 0.4f)
                     + __powf(fabsf(c2 - v2) + 0.01f, 0.4f));
    g_g1w[i] = (0.2989f * v0 + 0.587f * v1 + 0.114f * v2) * 255.0f;
    g_g2[i]  = (0.2989f * c0 + 0.587f * c1 + 0.114f * c2) * 255.0f;

    // block reduction: pfw, pbw, mfw, mbw
    float vals[4] = {pfw, pbw, mfw, mbw};
    __shared__ float red[8][4];
    int lane = threadIdx.x & 31, wid = threadIdx.x >> 5;
    #pragma unroll
    for (int k = 0; k < 4; k++) {
        float s = warp_reduce(vals[k]);
        if (lane == 0) red[wid][k] = s;
    }
    __syncthreads();
    if (threadIdx.x == 0) {
        float s0 = 0, s1 = 0, s2 = 0, s3 = 0;
        #pragma unroll
        for (int w = 0; w < 8; w++) { s0 += red[w][0]; s1 += red[w][1]; s2 += red[w][2]; s3 += red[w][3]; }
        atomicAdd(&g_acc[0], (double)s0);
        atomicAdd(&g_acc[1], (double)s1);
        atomicAdd(&g_acc[4], (double)s2);
        atomicAdd(&g_acc[5], (double)s3);
    }
}

// ---------------------------------------------------------------------------
// Census: direct 48-tap form with packed f32x2 (FFMA2) arithmetic.
// Lane pairing: lo lane = fw pair (img1, img2_warped), hi lane = bw pair
// (img2, img1_warped). Per tap both pairs run the identical chain, so the
// whole tap is 11 packed FMA-pipe ops + 4 scalar MUFU rsqrts + packed
// Newton reciprocal (seed = one u64 integer subtract: magic 0x7EF477D5
// exceeds any operand's float bits for x in (0.1, 5.1], so no borrow
// crosses the halves). MUFU is the binding pipe at ~1536 cyc/warp.
//   smem map A = (g1, g2)  -> packed d1 for (fw, bw)
//   smem map Bm = (g2w, g1w) -> packed d2 for (fw, bw)
// ---------------------------------------------------------------------------
constexpr int TX = 32, TY = 8;
constexpr int SW = TX + 6, SH = TY + 6;   // 38 x 14 value tile

__global__ void __launch_bounds__(256) k_census(const float* __restrict__ occ_fw) {
    __shared__ float2 sA[SH][SW];   // (g1,  g2)
    __shared__ float2 sB[SH][SW];   // (g2w, g1w)
    __shared__ float2 red[8];

    int b   = blockIdx.z;
    int bx0 = blockIdx.x * TX;
    int by0 = blockIdx.y * TY;
    const float* p1  = g_g1  + (size_t)b * HW;
    const float* p2w = g_g2w + (size_t)b * HW;
    const float* p2  = g_g2  + (size_t)b * HW;
    const float* p1w = g_g1w + (size_t)b * HW;

    int tid = threadIdx.y * TX + threadIdx.x;
    for (int t = tid; t < SH * SW; t += TX * TY) {
        int ly = t / SW, lx = t - ly * SW;
        int gy = by0 + ly - 3, gx = bx0 + lx - 3;
        float a = 0, bb = 0, c = 0, d = 0;
        if (gy >= 0 && gy < H && gx >= 0 && gx < W) {
            int gi = gy * W + gx;
            a = p1[gi]; bb = p2w[gi]; c = p2[gi]; d = p1w[gi];
        }
        sA[ly][lx] = make_float2(a, c);    // (g1, g2)
        sB[ly][lx] = make_float2(bb, d);   // (g2w, g1w)
    }
    __syncthreads();

    int lx = threadIdx.x, ly = threadIdx.y;
    float2 cA = sA[ly + 3][lx + 3];
    float2 cB = sB[ly + 3][lx + 3];
    u64 negcA = pack2(-cA.x, -cA.y);
    u64 negcB = pack2(-cB.x, -cB.y);

    const u64 c081  = pack2(0.81f, 0.81f);
    const u64 c01   = pack2(0.1f, 0.1f);
    const u64 c2    = pack2(2.0f, 2.0f);
    const u64 SIGN  = 0x8000000080000000ULL;
    const u64 MAGIC = 0x7EF477D57EF477D5ULL;

    u64 acc = 0;   // (dsf, dsb) packed; 0 == (0.0f, 0.0f)

    #pragma unroll
    for (int dy = 0; dy < 7; dy++) {
        #pragma unroll
        for (int dx = 0; dx < 7; dx++) {
            if (dy == 3 && dx == 3) continue;        // center tap == 0

            u64 nA = *(const u64*)&sA[ly + dy][lx + dx];
            u64 nB = *(const u64*)&sB[ly + dy][lx + dx];

            u64 d1 = add2(nA, negcA);                // (d1_fw, d1_bw)
            u64 d2 = add2(nB, negcB);                // (d2_fw, d2_bw)

            u64 a1 = fma2(d1, d1, c081);
            u64 a2 = fma2(d2, d2, c081);
            float a1l, a1h, a2l, a2h;
            unpack2(a1, a1l, a1h);
            unpack2(a2, a2l, a2h);
            u64 r1 = pack2(rsqrtf(a1l), rsqrtf(a1h));
            u64 r2 = pack2(rsqrtf(a2l), rsqrtf(a2h));

            u64 t1 = mul2(d1, r1);
            u64 t2 = mul2(d2, r2);
            u64 df = add2(t1, t2 ^ SIGN);            // t1 - t2
            u64 dd = mul2(df, df);
            u64 x  = add2(dd, c01);                  // 0.1 + dd, in (0.1, 5.1]

            // packed Newton reciprocal of x
            u64 s  = MAGIC - x;                      // per-half seed (no cross-borrow)
            u64 nx = x ^ SIGN;
            s = mul2(s, fma2(nx, s, c2));
            s = mul2(s, fma2(nx, s, c2));

            acc = fma2(dd, s, acc);                  // += dd / (0.1 + dd)
        }
    }

    float dsf, dsb;
    unpack2(acc, dsf, dsb);

    int gy = by0 + ly, gx = bx0 + lx;
    int i = b * HW + gy * W + gx;
    float maskf = 1.0f - occ_fw[i];
    float maskb = g_maskbw[i];
    float cfv = __powf(dsf + 0.01f, 0.4f) * maskf;
    float cbv = __powf(dsb + 0.01f, 0.4f) * maskb;

    int lane = tid & 31, wid = tid >> 5;
    float sf = warp_reduce(cfv);
    float sb = warp_reduce(cbv);
    if (lane == 0) red[wid] = make_float2(sf, sb);
    __syncthreads();
    if (tid == 0) {
        float a = 0, c = 0;
        #pragma unroll
        for (int w = 0; w < 8; w++) { a += red[w].x; c += red[w].y; }
        atomicAdd(&g_acc[2], (double)a);
        atomicAdd(&g_acc[3], (double)c);
    }
}

__global__ void k_final(float* __restrict__ out) {
    if (threadIdx.x == 0) {
        double dfw = g_acc[4] * 2.0 + 1e-6;
        double dbw = g_acc[5] * 2.0 + 1e-6;
        double photo  = g_acc[0] / dfw + g_acc[1] / dbw;
        double census = g_acc[2] / dfw + g_acc[3] / dbw;
        out[0] = (float)(photo + census);
        out[1] = (float)photo;
        out[2] = (float)census;
        // re-zero accumulators for the next call (graph replay safe:
        // globals are zero-initialized at load, and every call ends here)
        #pragma unroll
        for (int k = 0; k < 6; k++) g_acc[k] = 0.0;
    }
}

extern "C" void kernel_launch(void* const* d_in, const int* in_sizes, int n_in,
                              void* d_out, int out_size) {
    const float* img1 = (const float*)d_in[0];
    const float* img2 = (const float*)d_in[1];
    const float* ffw  = (const float*)d_in[2];
    const float* fbw  = (const float*)d_in[3];
    float* out = (float*)d_out;

    k_main<<<NPIX / 256, 256>>>(img1, img2, ffw, fbw, out);
    dim3 cg(W / TX, H / TY, B);
    dim3 cb(TX, TY, 1);
    k_census<<<cg, cb>>>(out + 3);
    k_final<<<1, 32>>>(out);
}